// round 3
// baseline (speedup 1.0000x reference)
#include <cuda_runtime.h>
#include <cuda_bf16.h>

// Problem constants (fixed shapes for this bench)
#define B_   16
#define C_   256
#define H_   224
#define W_   224
#define P_   14
#define NH_  16
#define NW_  16
#define N_   256          // NH_*NW_ patches
#define CC_  16           // channels per chunk
#define NCH_ 16           // C_/CC_
#define EPS_COS  1e-8f
#define EPS_NORM 1e-12f

// Scratch (written fully every launch; no init kernel needed)
__device__ float g_dot[NCH_ * B_ * N_];   // [chunk][b][n]
__device__ float g_nsq[NCH_ * B_ * N_];   // [chunk][b][n]
__device__ float g_qsq[NCH_ * B_];        // [chunk][b]
__device__ float g_loss[B_];

// ---------------------------------------------------------------------------
// Kernel 1: per (chunk, patch-row, batch) accumulate dot(t,q) and ||t||^2
// 224 active threads = 4 channel-groups (z) x 56 float4-columns (w4).
// Each thread streams 4 channels x 14 rows of float4 (LDG.128, fully aligned).
// ---------------------------------------------------------------------------
__global__ __launch_bounds__(256, 6)
void accum_kernel(const float* __restrict__ qf,
                  const float* __restrict__ rf,
                  const int*   __restrict__ click) {
    __shared__ float smq[CC_ * P_ * P_];   // 3136 floats = 12.25 KB  [cc][i][j]
    __shared__ float sdot[4 * 224];        // per-z per-column dot partials
    __shared__ float snsq[4 * 224];        // per-z per-column nsq partials

    const int chunk = blockIdx.x;
    const int ph    = blockIdx.y;
    const int b     = blockIdx.z;
    const int tid   = threadIdx.x;
    const int c0    = chunk * CC_;

    const int qx = click[2 * b + 0];
    const int qy = click[2 * b + 1];
    const int qh = qy / P_;
    const int qw = qx / P_;

    // Stage query patch tile (CC_ channels x 14 x 14) into smem
    const float* qbase = qf + ((size_t)(b * C_ + c0) * H_ + qh * P_) * W_ + qw * P_;
    for (int idx = tid; idx < CC_ * P_ * P_; idx += blockDim.x) {
        int cc = idx / (P_ * P_);
        int r  = idx - cc * (P_ * P_);
        int i  = r / P_;
        int j  = r - i * P_;
        smq[idx] = qbase[(cc * H_ + i) * W_ + j];
    }
    __syncthreads();

    if (tid < 224) {
        const int z    = tid / 56;        // channel group: channels z*4 .. z*4+3
        const int w4   = tid - z * 56;    // float4 column index
        const int col0 = 4 * w4;
        // per-element within-patch column index (handles patch crossing)
        const int j0 = (col0 + 0) % P_;
        const int j1 = (col0 + 1) % P_;
        const int j2 = (col0 + 2) % P_;
        const int j3 = (col0 + 3) % P_;

        const float4* tb = (const float4*)(rf +
            ((size_t)(b * C_ + c0 + z * 4) * H_ + ph * P_) * W_) + w4;

        float d0 = 0.f, d1 = 0.f, d2 = 0.f, d3 = 0.f;
        float s0 = 0.f, s1 = 0.f, s2 = 0.f, s3 = 0.f;

#pragma unroll
        for (int cc = 0; cc < 4; ++cc) {
            const float4* tp = tb + cc * (H_ * W_ / 4);
            const float*  qp = smq + (z * 4 + cc) * (P_ * P_);
#pragma unroll
            for (int i = 0; i < P_; ++i) {
                float4 v = __ldg(tp + i * (W_ / 4));
                const float* q = qp + i * P_;
                d0 = fmaf(v.x, q[j0], d0);  s0 = fmaf(v.x, v.x, s0);
                d1 = fmaf(v.y, q[j1], d1);  s1 = fmaf(v.y, v.y, s1);
                d2 = fmaf(v.z, q[j2], d2);  s2 = fmaf(v.z, v.z, s2);
                d3 = fmaf(v.w, q[j3], d3);  s3 = fmaf(v.w, v.w, s3);
            }
        }
        // aligned float4 stores into smem (z*224 and 4*w4 are both /4)
        *(float4*)(sdot + z * 224 + col0) = make_float4(d0, d1, d2, d3);
        *(float4*)(snsq + z * 224 + col0) = make_float4(s0, s1, s2, s3);
    }
    __syncthreads();

    // Reduce over channel groups (4) and the 14 columns of each patch
    if (tid < NW_) {
        float d = 0.f, s = 0.f;
#pragma unroll
        for (int z = 0; z < 4; ++z) {
#pragma unroll
            for (int k = 0; k < P_; ++k) {
                d += sdot[z * 224 + tid * P_ + k];
                s += snsq[z * 224 + tid * P_ + k];
            }
        }
        const int n = ph * NW_ + tid;
        g_dot[(chunk * B_ + b) * N_ + n] = d;
        g_nsq[(chunk * B_ + b) * N_ + n] = s;
    }

    // One patch-row's worth of CTAs (ph==0) also computes partial ||q||^2
    if (ph == 0) {
        __syncthreads();            // protect sdot reuse
        float acc = 0.f;
        for (int idx = tid; idx < CC_ * P_ * P_; idx += blockDim.x) {
            float v = smq[idx];
            acc = fmaf(v, v, acc);
        }
        sdot[tid] = acc;
        __syncthreads();
        for (int s = 128; s > 0; s >>= 1) {
            if (tid < s) sdot[tid] += sdot[tid + s];
            __syncthreads();
        }
        if (tid == 0) g_qsq[chunk * B_ + b] = sdot[0];
    }
}

// ---------------------------------------------------------------------------
// Kernel 2: per-batch cosine-sim -> normalize -> log-softmax -> loss_b
// ---------------------------------------------------------------------------
__global__ __launch_bounds__(256)
void finalizeA_kernel(const float* __restrict__ logit_scale,
                      const int*   __restrict__ gt) {
    const int b   = blockIdx.x;
    const int tid = threadIdx.x;
    __shared__ float sh[256];

    // ||q||^2 = sum of chunk partials
    sh[tid] = (tid < NCH_) ? g_qsq[tid * B_ + b] : 0.f;
    __syncthreads();
    for (int s = 128; s > 0; s >>= 1) {
        if (tid < s) sh[tid] += sh[tid + s];
        __syncthreads();
    }
    const float Qc = fmaxf(sqrtf(sh[0]), EPS_COS);
    __syncthreads();

    // Per-patch (n == tid) sums across chunks
    const int n = tid;
    float dot = 0.f, tsq = 0.f;
    for (int ch = 0; ch < NCH_; ++ch) {
        dot += g_dot[(ch * B_ + b) * N_ + n];
        tsq += g_nsq[(ch * B_ + b) * N_ + n];
    }
    float s_n = dot / (fmaxf(sqrtf(tsq), EPS_COS) * Qc);

    // F.normalize over the 256-wide sim vector
    sh[tid] = s_n * s_n;
    __syncthreads();
    for (int s = 128; s > 0; s >>= 1) {
        if (tid < s) sh[tid] += sh[tid + s];
        __syncthreads();
    }
    const float r = fmaxf(sqrtf(sh[0]), EPS_NORM);
    __syncthreads();

    const float l = logit_scale[0] * (s_n / r);

    // log-softmax: max
    sh[tid] = l;
    __syncthreads();
    for (int s = 128; s > 0; s >>= 1) {
        if (tid < s) sh[tid] = fmaxf(sh[tid], sh[tid + s]);
        __syncthreads();
    }
    const float m = sh[0];
    __syncthreads();

    // sum exp
    sh[tid] = __expf(l - m);
    __syncthreads();
    for (int s = 128; s > 0; s >>= 1) {
        if (tid < s) sh[tid] += sh[tid + s];
        __syncthreads();
    }
    const float lse = m + logf(sh[0]);

    const int gx = gt[2 * b + 0];
    const int gy = gt[2 * b + 1];
    const int label = (gy / P_) * NW_ + (gx / P_);
    if (n == label) g_loss[b] = lse - l;   // -logp[label]
}

// ---------------------------------------------------------------------------
// Kernel 3: mean over batches
// ---------------------------------------------------------------------------
__global__ void finalizeB_kernel(float* __restrict__ out) {
    if (threadIdx.x == 0) {
        float acc = 0.f;
        for (int b = 0; b < B_; ++b) acc += g_loss[b];
        out[0] = acc / (float)B_;
    }
}

// ---------------------------------------------------------------------------
extern "C" void kernel_launch(void* const* d_in, const int* in_sizes, int n_in,
                              void* d_out, int out_size) {
    const float* qf    = (const float*)d_in[0];   // query_feature [16,256,224,224]
    const float* rf    = (const float*)d_in[1];   // ref_feature   [16,256,224,224]
    const float* scale = (const float*)d_in[2];   // logit_scale scalar
    const int*   click = (const int*)  d_in[3];   // click_points [16,2] int32
    const int*   gt    = (const int*)  d_in[4];   // gt_points    [16,2] int32
    // d_in[5] = patch_size (14), fixed -> hardcoded

    dim3 grid(NCH_, NH_, B_);
    accum_kernel<<<grid, 256>>>(qf, rf, click);
    finalizeA_kernel<<<B_, 256>>>(scale, gt);
    finalizeB_kernel<<<1, 32>>>((float*)d_out);
}

// round 4
// speedup vs baseline: 1.1028x; 1.1028x over previous
#include <cuda_runtime.h>
#include <cuda_bf16.h>

// Problem constants (fixed shapes for this bench)
#define B_   16
#define C_   256
#define H_   224
#define W_   224
#define P_   14
#define NH_  16
#define NW_  16
#define N_   256          // NH_*NW_ patches
#define CC_  8            // channels per chunk (halved for wave-quantization fix)
#define NCH_ 32           // C_/CC_
#define EPS_COS  1e-8f
#define EPS_NORM 1e-12f

// Scratch (written fully every launch; no init kernel needed)
__device__ float g_dot[NCH_ * B_ * N_];   // [chunk][b][n]
__device__ float g_nsq[NCH_ * B_ * N_];   // [chunk][b][n]
__device__ float g_qsq[NCH_ * B_];        // [chunk][b]
__device__ float g_loss[B_];

// ---------------------------------------------------------------------------
// Kernel 1: per (chunk, patch-row, batch) accumulate dot(t,q) and ||t||^2
// ---------------------------------------------------------------------------
__global__ __launch_bounds__(256)
void accum_kernel(const float* __restrict__ qf,
                  const float* __restrict__ rf,
                  const int*   __restrict__ click) {
    __shared__ float smq[CC_ * P_ * P_];   // 1568 floats = 6.125 KB
    __shared__ float sred[2 * 224];

    const int chunk = blockIdx.x;
    const int ph    = blockIdx.y;
    const int b     = blockIdx.z;
    const int tid   = threadIdx.x;
    const int c0    = chunk * CC_;

    const int qx = click[2 * b + 0];
    const int qy = click[2 * b + 1];
    const int qh = qy / P_;
    const int qw = qx / P_;

    // Stage query patch tile (CC_ channels x 14 x 14) into smem
    const float* qbase = qf + ((size_t)(b * C_ + c0) * H_ + qh * P_) * W_ + qw * P_;
    for (int idx = tid; idx < CC_ * P_ * P_; idx += blockDim.x) {
        int cc = idx / (P_ * P_);
        int r  = idx - cc * (P_ * P_);
        int i  = r / P_;
        int j  = r - i * P_;
        smq[idx] = qbase[(cc * H_ + i) * W_ + j];
    }
    __syncthreads();

    // Each thread owns one image column w in [0,224): perfectly coalesced
    // 128B-per-warp loads of ref_feature rows.
    const int w = tid;
    if (w < W_) {
        const int pw = w / P_;
        const int j  = w - pw * P_;
        const float* tbase = rf + ((size_t)(b * C_ + c0) * H_ + ph * P_) * W_ + w;
        float dot = 0.f, nsq = 0.f;
#pragma unroll
        for (int cc = 0; cc < CC_; ++cc) {
            const float* tp = tbase + cc * (H_ * W_);
            const float* qp = smq + cc * (P_ * P_) + j;
#pragma unroll
            for (int i = 0; i < P_; ++i) {
                float t  = __ldcs(tp + i * W_);   // streaming, evict-first
                float qv = qp[i * P_];
                dot = fmaf(t, qv, dot);
                nsq = fmaf(t, t, nsq);
            }
        }
        sred[w]       = dot;
        sred[224 + w] = nsq;
    }
    __syncthreads();

    // Reduce 14 columns -> one patch; write disjoint slots (no atomics)
    if (tid < NW_) {
        float d = 0.f, s = 0.f;
#pragma unroll
        for (int k = 0; k < P_; ++k) {
            d += sred[tid * P_ + k];
            s += sred[224 + tid * P_ + k];
        }
        const int n = ph * NW_ + tid;
        g_dot[(chunk * B_ + b) * N_ + n] = d;
        g_nsq[(chunk * B_ + b) * N_ + n] = s;
    }

    // One patch-row's worth of CTAs (ph==0) also computes partial ||q||^2
    if (ph == 0) {
        __syncthreads();            // protect sred reuse
        float acc = 0.f;
        for (int idx = tid; idx < CC_ * P_ * P_; idx += blockDim.x) {
            float v = smq[idx];
            acc = fmaf(v, v, acc);
        }
        sred[tid] = acc;
        __syncthreads();
        for (int s = 128; s > 0; s >>= 1) {
            if (tid < s) sred[tid] += sred[tid + s];
            __syncthreads();
        }
        if (tid == 0) g_qsq[chunk * B_ + b] = sred[0];
    }
}

// ---------------------------------------------------------------------------
// Kernel 2: per-batch cosine-sim -> normalize -> log-softmax -> loss_b
// ---------------------------------------------------------------------------
__global__ __launch_bounds__(256)
void finalizeA_kernel(const float* __restrict__ logit_scale,
                      const int*   __restrict__ gt) {
    const int b   = blockIdx.x;
    const int tid = threadIdx.x;
    __shared__ float sh[256];

    // ||q||^2 = sum of chunk partials
    sh[tid] = (tid < NCH_) ? g_qsq[tid * B_ + b] : 0.f;
    __syncthreads();
    for (int s = 128; s > 0; s >>= 1) {
        if (tid < s) sh[tid] += sh[tid + s];
        __syncthreads();
    }
    const float Qc = fmaxf(sqrtf(sh[0]), EPS_COS);
    __syncthreads();

    // Per-patch (n == tid) sums across chunks
    const int n = tid;
    float dot = 0.f, tsq = 0.f;
#pragma unroll 8
    for (int ch = 0; ch < NCH_; ++ch) {
        dot += g_dot[(ch * B_ + b) * N_ + n];
        tsq += g_nsq[(ch * B_ + b) * N_ + n];
    }
    float s_n = dot / (fmaxf(sqrtf(tsq), EPS_COS) * Qc);

    // F.normalize over the 256-wide sim vector
    sh[tid] = s_n * s_n;
    __syncthreads();
    for (int s = 128; s > 0; s >>= 1) {
        if (tid < s) sh[tid] += sh[tid + s];
        __syncthreads();
    }
    const float r = fmaxf(sqrtf(sh[0]), EPS_NORM);
    __syncthreads();

    const float l = logit_scale[0] * (s_n / r);

    // log-softmax: max
    sh[tid] = l;
    __syncthreads();
    for (int s = 128; s > 0; s >>= 1) {
        if (tid < s) sh[tid] = fmaxf(sh[tid], sh[tid + s]);
        __syncthreads();
    }
    const float m = sh[0];
    __syncthreads();

    // sum exp
    sh[tid] = __expf(l - m);
    __syncthreads();
    for (int s = 128; s > 0; s >>= 1) {
        if (tid < s) sh[tid] += sh[tid + s];
        __syncthreads();
    }
    const float lse = m + logf(sh[0]);

    const int gx = gt[2 * b + 0];
    const int gy = gt[2 * b + 1];
    const int label = (gy / P_) * NW_ + (gx / P_);
    if (n == label) g_loss[b] = lse - l;   // -logp[label]
}

// ---------------------------------------------------------------------------
// Kernel 3: mean over batches
// ---------------------------------------------------------------------------
__global__ void finalizeB_kernel(float* __restrict__ out) {
    if (threadIdx.x == 0) {
        float acc = 0.f;
        for (int b = 0; b < B_; ++b) acc += g_loss[b];
        out[0] = acc / (float)B_;
    }
}

// ---------------------------------------------------------------------------
extern "C" void kernel_launch(void* const* d_in, const int* in_sizes, int n_in,
                              void* d_out, int out_size) {
    const float* qf    = (const float*)d_in[0];   // query_feature [16,256,224,224]
    const float* rf    = (const float*)d_in[1];   // ref_feature   [16,256,224,224]
    const float* scale = (const float*)d_in[2];   // logit_scale scalar
    const int*   click = (const int*)  d_in[3];   // click_points [16,2] int32
    const int*   gt    = (const int*)  d_in[4];   // gt_points    [16,2] int32
    // d_in[5] = patch_size (14), fixed -> hardcoded

    dim3 grid(NCH_, NH_, B_);
    accum_kernel<<<grid, 256>>>(qf, rf, click);
    finalizeA_kernel<<<B_, 256>>>(scale, gt);
    finalizeB_kernel<<<1, 32>>>((float*)d_out);
}